// round 13
// baseline (speedup 1.0000x reference)
#include <cuda_runtime.h>

// Problem dims (fixed by reference setup_inputs)
#define B_DIM 8192
#define T_DIM 2048
#define H     20
#define CTA_ROWS 32       // batch rows per CTA (1 row per lane)
#define NTHR  256         // 8 warps; warps 0-3 own 3 units, warps 4-7 own 2
#define NCTA  (B_DIM / CTA_ROWS)   // 256 CTAs -> 2 per SM, drifting freely
#define PSRC  2           // source units pinned in registers (reg-ceiling 128!)

typedef unsigned long long u64;

// Scratch (allocation-free rule: __device__ globals)
__device__ float g_xT[(size_t)T_DIM * B_DIM];   // x transposed: [t][b]
__device__ float g_outT[(size_t)T_DIM * B_DIM]; // out transposed: [t][b]

// ---------------- f32x2 helpers ----------------
__device__ __forceinline__ u64 pk(float lo, float hi) {
    u64 r; asm("mov.b64 %0,{%1,%2};" : "=l"(r) : "f"(lo), "f"(hi)); return r;
}
__device__ __forceinline__ void upk(u64 v, float& lo, float& hi) {
    asm("mov.b64 {%0,%1},%2;" : "=f"(lo), "=f"(hi) : "l"(v));
}
__device__ __forceinline__ u64 fma2(u64 a, u64 b, u64 c) {
    u64 d; asm("fma.rn.f32x2 %0,%1,%2,%3;" : "=l"(d) : "l"(a), "l"(b), "l"(c)); return d;
}
__device__ __forceinline__ float tanh_a(float x) {
    float r; asm("tanh.approx.f32 %0,%1;" : "=f"(r) : "f"(x)); return r;
}

// LSTM cell via MUFU.TANH: 5 MUFU + ~9 FMA-pipe ops.
__device__ __forceinline__ void cell(float ig, float fg, float gg, float og,
                                     float& c, float& h) {
    float si = fmaf(0.5f, tanh_a(0.5f * ig), 0.5f);
    float sf = fmaf(0.5f, tanh_a(0.5f * fg), 0.5f);
    float so = fmaf(0.5f, tanh_a(0.5f * og), 0.5f);
    float tg = tanh_a(gg);
    float cn = sf * c + si * tg;
    float tc = tanh_a(cn);
    c = cn;
    h = so * tc;
}

// ---------------- transposes ----------------
__global__ void transpose_in(const float* __restrict__ in) {
    __shared__ float tile[32][33];
    int c0 = blockIdx.x * 32, r0 = blockIdx.y * 32;
    int tx = threadIdx.x, ty = threadIdx.y;
#pragma unroll
    for (int i = 0; i < 32; i += 8)
        tile[ty + i][tx] = in[(size_t)(r0 + ty + i) * T_DIM + c0 + tx];
    __syncthreads();
#pragma unroll
    for (int i = 0; i < 32; i += 8)
        g_xT[(size_t)(c0 + ty + i) * B_DIM + r0 + tx] = tile[tx][ty + i];
}

__global__ void transpose_out(float* __restrict__ out) {
    __shared__ float tile[32][33];
    int c0 = blockIdx.x * 32, r0 = blockIdx.y * 32;
    int tx = threadIdx.x, ty = threadIdx.y;
#pragma unroll
    for (int i = 0; i < 32; i += 8)
        tile[ty + i][tx] = g_outT[(size_t)(r0 + ty + i) * B_DIM + c0 + tx];
    __syncthreads();
#pragma unroll
    for (int i = 0; i < 32; i += 8)
        out[(size_t)(c0 + ty + i) * T_DIM + r0 + tx] = tile[tx][ty + i];
}

// Slot -> (gate-row ka, gate-row kb) mapping.
// Warps 0-3: units ub=3w,3w+1,3w+2. Slots 0-3: gate s of pair (ub,ub+1).
//            Slot 4: (i,f) of ub+2. Slot 5: (g,o) of ub+2.
// Warps 4-7: units ub=12+2(w-4). Slots 0-3 only.
__device__ __forceinline__ bool slot_rows(int w, int s, int& ka, int& kb) {
    if (w < 4) {
        int ub = 3 * w;
        if (s < 4)      { ka = s * H + ub;     kb = ka + 1; }
        else if (s == 4){ ka = 0 * H + ub + 2; kb = 1 * H + ub + 2; }
        else            { ka = 2 * H + ub + 2; kb = 3 * H + ub + 2; }
        return true;
    } else {
        int ub = 12 + 2 * (w - 4);
        if (s < 4) { ka = s * H + ub; kb = ka + 1; return true; }
        return false;
    }
}

// ---------------- main persistent LSTM kernel ----------------
// 256 CTAs x 256 threads (8 warps). CTA owns 32 rows; lane = row.
// TWO independent CTAs co-resident per SM (4 warps/SMSP): their barriers are
// private, so the recurrences drift and fill each other's latency shadows
// (cell chains, post-barrier LDS, MUFU) without sharing any weight stream.
// SMSP-balanced unit assignment (3+2 units); one __syncthreads per step.
// Register ceiling is 128/thread at occupancy 2 -> PSRC kept small, enforced
// via __launch_bounds__(256, 2).
//
// ROUND-12 BUG FIX: the out-projection packs TWO DIFFERENT UNITS per f32x2
// (hv[2j], hv[2j+1]) and therefore needs the PAIRED W2 table
// w2q[j] = (W2[2j], W2[2j+1]) — not the duplicated w2p from round 11.
__global__ __launch_bounds__(NTHR, 2) void lstm_kernel(
    const float* __restrict__ W1, const float* __restrict__ b1,
    const float* __restrict__ W_ih, const float* __restrict__ W_hh,
    const float* __restrict__ b_ih, const float* __restrict__ b_hh,
    const float* __restrict__ W2, const float* __restrict__ b2)
{
    __shared__ __align__(16) u64 WQ[H][8][6];     // [src][warp][slot]  7.7 KB
    __shared__ __align__(16) u64 uvu[8][6], uvv[8][6];
    __shared__ u64 w2q[10];                       // (W2[2j], W2[2j+1]) PAIRED
    __shared__ float b2_s;
    __shared__ float h_s[2][H][CTA_ROWS];         // 5.1 KB

    const int tid  = threadIdx.x;
    const int lane = tid & 31;
    const int wid  = tid >> 5;
    const int grow = blockIdx.x * CTA_ROWS + lane;   // this lane's global row

    // --- one-time setup ---
    for (int i = tid; i < H * 48; i += NTHR) {
        int src = i / 48, r = i % 48, w = r / 6, s = r % 6;
        int ka, kb;
        WQ[src][w][s] = slot_rows(w, s, ka, kb)
            ? pk(W_hh[ka * H + src], W_hh[kb * H + src]) : 0ULL;
    }
    if (tid < 48) {
        int w = tid / 6, s = tid % 6, ka, kb;
        if (slot_rows(w, s, ka, kb)) {
            float sua = 0.f, sva = 0.f, sub = 0.f, svb = 0.f;
            for (int u = 0; u < H; ++u) {
                sua += W_ih[ka * H + u] * W1[u];
                sva += W_ih[ka * H + u] * b1[u];
                sub += W_ih[kb * H + u] * W1[u];
                svb += W_ih[kb * H + u] * b1[u];
            }
            uvu[w][s] = pk(sua, sub);
            uvv[w][s] = pk(sva + b_ih[ka] + b_hh[ka], svb + b_ih[kb] + b_hh[kb]);
        } else { uvu[w][s] = 0ULL; uvv[w][s] = 0ULL; }
    }
    if (tid < 10) w2q[tid] = pk(W2[2 * tid], W2[2 * tid + 1]);   // PAIRED
    if (tid == 0) b2_s = b2[0];
    for (int i = tid; i < 2 * H * CTA_ROWS; i += NTHR) h_s[0][0][i] = 0.f;
    __syncthreads();

    const int ub = (wid < 4) ? 3 * wid : 12 + 2 * (wid - 4);

    // per-warp register tables (6 slots, light warps just ignore 4/5)
    u64 uu[6], vv[6];
#pragma unroll
    for (int s = 0; s < 6; ++s) { uu[s] = uvu[wid][s]; vv[s] = uvv[wid][s]; }

    // pinned weights for sources [0, PSRC): small, to stay under 128 regs
    u64 wp[PSRC][6];
#pragma unroll
    for (int u = 0; u < PSRC; ++u)
#pragma unroll
        for (int s = 0; s < 6; ++s) wp[u][s] = WQ[u][wid][s];

    u64 c2[3] = {0ULL, 0ULL, 0ULL};   // cell state per owned unit (lo half used)

    float xv = g_xT[grow];

    for (int t = 0; t < T_DIM; ++t) {
        const int cur = t & 1, nxt = cur ^ 1;

        float xnext = xv;
        if (t + 1 < T_DIM)
            xnext = g_xT[(size_t)(t + 1) * B_DIM + grow];

        // ---- preload full h vector: 20 coalesced LDS.32 (1 wf each) ----
        float hv[H];
#pragma unroll
        for (int u = 0; u < H; ++u)
            hv[u] = h_s[cur][u][lane];

        // ---- out[t-1]: light warp 4 reuses hv registers (PAIRED w2q) ----
        if (wid == 4 && t > 0) {
            u64 oacc = pk(b2_s, 0.f);
#pragma unroll
            for (int j = 0; j < 10; ++j)
                oacc = fma2(w2q[j], pk(hv[2 * j], hv[2 * j + 1]), oacc);
            float o0, o1; upk(oacc, o0, o1);
            g_outT[(size_t)(t - 1) * B_DIM + grow] = o0 + o1;
        }

        u64 x2 = pk(xv, xv);

        if (wid < 4) {
            // ===== heavy path: 3 units, 6 slots =====
            u64 a[6];
#pragma unroll
            for (int s = 0; s < 6; ++s) a[s] = fma2(x2, uu[s], vv[s]);
#pragma unroll
            for (int u = 0; u < PSRC; ++u) {
                u64 hp = pk(hv[u], hv[u]);
#pragma unroll
                for (int s = 0; s < 6; ++s) a[s] = fma2(wp[u][s], hp, a[s]);
            }
#pragma unroll
            for (int u = PSRC; u < H; ++u) {
                u64 hp = pk(hv[u], hv[u]);
                ulonglong2 q0 = *(const ulonglong2*)&WQ[u][wid][0];
                ulonglong2 q1 = *(const ulonglong2*)&WQ[u][wid][2];
                ulonglong2 q2 = *(const ulonglong2*)&WQ[u][wid][4];
                a[0] = fma2(q0.x, hp, a[0]);  a[1] = fma2(q0.y, hp, a[1]);
                a[2] = fma2(q1.x, hp, a[2]);  a[3] = fma2(q1.y, hp, a[3]);
                a[4] = fma2(q2.x, hp, a[4]);  a[5] = fma2(q2.y, hp, a[5]);
            }
            // cells: units ub, ub+1 from slots 0-3; unit ub+2 from slots 4,5
            float i0,i1,f0,f1,g0,g1,o0,o1;
            upk(a[0],i0,i1); upk(a[1],f0,f1); upk(a[2],g0,g1); upk(a[3],o0,o1);
            float if0,if1,go0,go1;
            upk(a[4],if0,if1); upk(a[5],go0,go1);

            float cA, cD, hA;
            upk(c2[0], cA, cD);
            cell(i0, f0, g0, o0, cA, hA);
            c2[0] = pk(cA, cD);
            h_s[nxt][ub][lane] = hA;

            upk(c2[1], cA, cD);
            cell(i1, f1, g1, o1, cA, hA);
            c2[1] = pk(cA, cD);
            h_s[nxt][ub + 1][lane] = hA;

            upk(c2[2], cA, cD);
            cell(if0, if1, go0, go1, cA, hA);
            c2[2] = pk(cA, cD);
            h_s[nxt][ub + 2][lane] = hA;
        } else {
            // ===== light path: 2 units, 4 slots =====
            u64 a[4];
#pragma unroll
            for (int s = 0; s < 4; ++s) a[s] = fma2(x2, uu[s], vv[s]);
#pragma unroll
            for (int u = 0; u < PSRC; ++u) {
                u64 hp = pk(hv[u], hv[u]);
#pragma unroll
                for (int s = 0; s < 4; ++s) a[s] = fma2(wp[u][s], hp, a[s]);
            }
#pragma unroll
            for (int u = PSRC; u < H; ++u) {
                u64 hp = pk(hv[u], hv[u]);
                ulonglong2 q0 = *(const ulonglong2*)&WQ[u][wid][0];
                ulonglong2 q1 = *(const ulonglong2*)&WQ[u][wid][2];
                a[0] = fma2(q0.x, hp, a[0]);  a[1] = fma2(q0.y, hp, a[1]);
                a[2] = fma2(q1.x, hp, a[2]);  a[3] = fma2(q1.y, hp, a[3]);
            }
            float i0,i1,f0,f1,g0,g1,o0,o1;
            upk(a[0],i0,i1); upk(a[1],f0,f1); upk(a[2],g0,g1); upk(a[3],o0,o1);

            float cA, cD, hA;
            upk(c2[0], cA, cD);
            cell(i0, f0, g0, o0, cA, hA);
            c2[0] = pk(cA, cD);
            h_s[nxt][ub][lane] = hA;

            upk(c2[1], cA, cD);
            cell(i1, f1, g1, o1, cA, hA);
            c2[1] = pk(cA, cD);
            h_s[nxt][ub + 1][lane] = hA;
        }

        // single barrier per step (CTA-private; co-resident CTA drifts freely)
        __syncthreads();

        xv = xnext;
    }

    // final out[T-1] from buffer (T_DIM & 1) — PAIRED w2q here too
    if (wid == 4) {
        const int cur = T_DIM & 1;
        u64 oacc = pk(b2_s, 0.f);
#pragma unroll
        for (int j = 0; j < 10; ++j)
            oacc = fma2(w2q[j],
                        pk(h_s[cur][2 * j][lane], h_s[cur][2 * j + 1][lane]),
                        oacc);
        float o0, o1; upk(oacc, o0, o1);
        g_outT[(size_t)(T_DIM - 1) * B_DIM + grow] = o0 + o1;
    }
}

// ---------------- launcher ----------------
extern "C" void kernel_launch(void* const* d_in, const int* in_sizes, int n_in,
                              void* d_out, int out_size)
{
    const float* x    = (const float*)d_in[0];
    const float* W1   = (const float*)d_in[1];
    const float* b1   = (const float*)d_in[2];
    const float* W_ih = (const float*)d_in[3];
    const float* W_hh = (const float*)d_in[4];
    const float* b_ih = (const float*)d_in[5];
    const float* b_hh = (const float*)d_in[6];
    const float* W2   = (const float*)d_in[7];
    const float* b2   = (const float*)d_in[8];
    float* out = (float*)d_out;

    (void)in_sizes; (void)n_in; (void)out_size;

    // x[B][T] -> g_xT[T][B]
    transpose_in<<<dim3(T_DIM / 32, B_DIM / 32), dim3(32, 8)>>>(x);

    // recurrent scan: 256 CTAs x 256 threads, 2 drifting CTAs per SM
    lstm_kernel<<<NCTA, NTHR>>>(W1, b1, W_ih, W_hh, b_ih, b_hh, W2, b2);

    // g_outT[T][B] -> out[B][T]
    transpose_out<<<dim3(B_DIM / 32, T_DIM / 32), dim3(32, 8)>>>(out);
}

// round 14
// speedup vs baseline: 1.3449x; 1.3449x over previous
#include <cuda_runtime.h>

// Problem dims (fixed by reference setup_inputs)
#define B_DIM 8192
#define T_DIM 2048
#define H     20
#define CTA_ROWS 64       // batch rows per CTA; lane owns rows (2l, 2l+1)
#define NTHR  384         // 12 warps: 8 pair-warps (2 units) + 4 solo (1 unit)
#define PSRC  4           // source units pinned in registers (170-reg ceiling)

typedef unsigned long long u64;

// Scratch (allocation-free rule: __device__ globals)
__device__ float g_xT[(size_t)T_DIM * B_DIM];   // x transposed: [t][b]
__device__ float g_outT[(size_t)T_DIM * B_DIM]; // out transposed: [t][b]

// ---------------- f32x2 helpers ----------------
__device__ __forceinline__ u64 pk(float lo, float hi) {
    u64 r; asm("mov.b64 %0,{%1,%2};" : "=l"(r) : "f"(lo), "f"(hi)); return r;
}
__device__ __forceinline__ void upk(u64 v, float& lo, float& hi) {
    asm("mov.b64 {%0,%1},%2;" : "=f"(lo), "=f"(hi) : "l"(v));
}
__device__ __forceinline__ u64 fma2(u64 a, u64 b, u64 c) {
    u64 d; asm("fma.rn.f32x2 %0,%1,%2,%3;" : "=l"(d) : "l"(a), "l"(b), "l"(c)); return d;
}
__device__ __forceinline__ float tanh_a(float x) {
    float r; asm("tanh.approx.f32 %0,%1;" : "=f"(r) : "f"(x)); return r;
}

// LSTM cell via MUFU.TANH: 5 MUFU + ~9 FMA-pipe ops.
__device__ __forceinline__ void cell(float ig, float fg, float gg, float og,
                                     float& c, float& h) {
    float si = fmaf(0.5f, tanh_a(0.5f * ig), 0.5f);
    float sf = fmaf(0.5f, tanh_a(0.5f * fg), 0.5f);
    float so = fmaf(0.5f, tanh_a(0.5f * og), 0.5f);
    float tg = tanh_a(gg);
    float cn = sf * c + si * tg;
    float tc = tanh_a(cn);
    c = cn;
    h = so * tc;
}

// ---------------- transposes ----------------
__global__ void transpose_in(const float* __restrict__ in) {
    __shared__ float tile[32][33];
    int c0 = blockIdx.x * 32, r0 = blockIdx.y * 32;
    int tx = threadIdx.x, ty = threadIdx.y;
#pragma unroll
    for (int i = 0; i < 32; i += 8)
        tile[ty + i][tx] = in[(size_t)(r0 + ty + i) * T_DIM + c0 + tx];
    __syncthreads();
#pragma unroll
    for (int i = 0; i < 32; i += 8)
        g_xT[(size_t)(c0 + ty + i) * B_DIM + r0 + tx] = tile[tx][ty + i];
}

__global__ void transpose_out(float* __restrict__ out) {
    __shared__ float tile[32][33];
    int c0 = blockIdx.x * 32, r0 = blockIdx.y * 32;
    int tx = threadIdx.x, ty = threadIdx.y;
#pragma unroll
    for (int i = 0; i < 32; i += 8)
        tile[ty + i][tx] = g_outT[(size_t)(r0 + ty + i) * B_DIM + c0 + tx];
    __syncthreads();
#pragma unroll
    for (int i = 0; i < 32; i += 8)
        out[(size_t)(c0 + ty + i) * T_DIM + r0 + tx] = tile[tx][ty + i];
}

// Slot -> (gate-row ka, gate-row kb).
// Warps 0-7 (pair warps, units 2w & 2w+1): slot s in 0..3 = gate s of the
//   unit pair: ka = s*H + 2w, kb = ka+1.
// Warps 8-11 (solo warps, unit 16+(w-8)): slot 0 = (i,f), slot 1 = (g,o).
__device__ __forceinline__ bool slot_rows12(int w, int s, int& ka, int& kb) {
    if (w < 8) { ka = s * H + 2 * w; kb = ka + 1; return true; }
    int ub = 16 + (w - 8);
    if (s == 0) { ka = 0 * H + ub; kb = 1 * H + ub; return true; }
    if (s == 1) { ka = 2 * H + ub; kb = 3 * H + ub; return true; }
    return false;
}

// ---------------- main persistent LSTM kernel ----------------
// 128 CTAs x 384 threads (12 warps). CTA owns 64 rows; lane owns 2 rows.
// Units covered exactly ONCE per CTA (the weight-stream law). SMSP k runs
// warps {k, k+4, k+8} = 2+2+1 = 5 units -> FMA balanced at ~840 cyc/SMSP,
// with THREE warp streams per SMSP to hide LDS/MUFU/barrier latency
// (round 11 had two). One __syncthreads per step; h double-buffered.
// Out-projection rotates across solo warps 8-11 (t&3); it packs (same unit,
// two rows) so the DUPLICATED w2p table is the correct one.
__global__ __launch_bounds__(NTHR, 1) void lstm_kernel(
    const float* __restrict__ W1, const float* __restrict__ b1,
    const float* __restrict__ W_ih, const float* __restrict__ W_hh,
    const float* __restrict__ b_ih, const float* __restrict__ b_hh,
    const float* __restrict__ W2, const float* __restrict__ b2)
{
    __shared__ __align__(16) u64 WQ[H][12][4];    // [src][warp][slot]  7.7 KB
    __shared__ __align__(16) u64 uvu[12][4], uvv[12][4];
    __shared__ u64 w2p[H];                        // (W2[u], W2[u]) duplicated
    __shared__ float b2_s;
    __shared__ __align__(8) float h_s[2][H][CTA_ROWS];  // 10.2 KB

    const int tid  = threadIdx.x;
    const int lane = tid & 31;
    const int wid  = tid >> 5;
    const int rowbase = blockIdx.x * CTA_ROWS;
    const int rA = 2 * lane;                      // rows owned by this lane

    // --- one-time setup ---
    for (int i = tid; i < H * 48; i += NTHR) {
        int src = i / 48, r = i % 48, w = r >> 2, s = r & 3;
        int ka, kb;
        WQ[src][w][s] = slot_rows12(w, s, ka, kb)
            ? pk(W_hh[ka * H + src], W_hh[kb * H + src]) : 0ULL;
    }
    if (tid < 48) {
        int w = tid >> 2, s = tid & 3, ka, kb;
        if (slot_rows12(w, s, ka, kb)) {
            float sua = 0.f, sva = 0.f, sub = 0.f, svb = 0.f;
            for (int u = 0; u < H; ++u) {
                sua += W_ih[ka * H + u] * W1[u];
                sva += W_ih[ka * H + u] * b1[u];
                sub += W_ih[kb * H + u] * W1[u];
                svb += W_ih[kb * H + u] * b1[u];
            }
            uvu[w][s] = pk(sua, sub);
            uvv[w][s] = pk(sva + b_ih[ka] + b_hh[ka], svb + b_ih[kb] + b_hh[kb]);
        } else { uvu[w][s] = 0ULL; uvv[w][s] = 0ULL; }
    }
    if (tid < H) { float wv = W2[tid]; w2p[tid] = pk(wv, wv); }
    if (tid == 0) b2_s = b2[0];
    for (int i = tid; i < 2 * H * CTA_ROWS; i += NTHR) h_s[0][0][i] = 0.f;
    __syncthreads();

    const bool is_pair = (wid < 8);
    const int ub = is_pair ? 2 * wid : 16 + (wid - 8);
    const int nslot = is_pair ? 4 : 2;

    // per-warp register tables
    u64 uu[4], vv[4];
#pragma unroll
    for (int s = 0; s < 4; ++s) { uu[s] = uvu[wid][s]; vv[s] = uvv[wid][s]; }

    // pinned weights for sources [0, PSRC)
    u64 wp[PSRC][4];
#pragma unroll
    for (int u = 0; u < PSRC; ++u)
#pragma unroll
        for (int s = 0; s < 4; ++s) wp[u][s] = WQ[u][wid][s];

    // cell state: pair warps use c2[0] (unit ub) and c2[1] (unit ub+1);
    // solo warps use c2[0] (unit ub). Each u64 = (rowA, rowB).
    u64 c2[2] = {0ULL, 0ULL};

    float2 xv = *(const float2*)(g_xT + rowbase + rA);

    for (int t = 0; t < T_DIM; ++t) {
        const int cur = t & 1, nxt = cur ^ 1;

        float2 xnext = xv;
        if (t + 1 < T_DIM)
            xnext = *(const float2*)(g_xT + (size_t)(t + 1) * B_DIM + rowbase + rA);

        // ---- preload full h vector: 20 conflict-free LDS.64 ----
        u64 h2[H];
#pragma unroll
        for (int u = 0; u < H; ++u)
            h2[u] = *(const u64*)&h_s[cur][u][rA];

        // ---- out[t-1]: rotate across solo warps 8-11 (spread the load).
        // (same unit, two rows) packing -> duplicated w2p is correct. ----
        if (t > 0 && wid == 8 + (t & 3)) {
            u64 oacc = pk(b2_s, b2_s);
#pragma unroll
            for (int u = 0; u < H; ++u)
                oacc = fma2(w2p[u], h2[u], oacc);     // (outA, outB)
            float o0, o1; upk(oacc, o0, o1);
            *(float2*)(g_outT + (size_t)(t - 1) * B_DIM + rowbase + rA) =
                make_float2(o0, o1);
        }

        u64 xA2 = pk(xv.x, xv.x), xB2 = pk(xv.y, xv.y);

        // ---- gate accumulation (nslot slots, rowsets A and B) ----
        u64 aA[4], aB[4];
#pragma unroll
        for (int s = 0; s < 4; ++s) {
            if (s < nslot) {
                aA[s] = fma2(xA2, uu[s], vv[s]);
                aB[s] = fma2(xB2, uu[s], vv[s]);
            } else { aA[s] = 0ULL; aB[s] = 0ULL; }
        }
#pragma unroll
        for (int u = 0; u < PSRC; ++u) {
            float hA, hB; upk(h2[u], hA, hB);
            u64 hpA = pk(hA, hA), hpB = pk(hB, hB);
#pragma unroll
            for (int s = 0; s < 4; ++s) {
                if (s < 2 || is_pair) {   // solo warps only need slots 0,1
                    aA[s] = fma2(wp[u][s], hpA, aA[s]);
                    aB[s] = fma2(wp[u][s], hpB, aB[s]);
                }
            }
        }
        if (is_pair) {
#pragma unroll
            for (int u = PSRC; u < H; ++u) {
                float hA, hB; upk(h2[u], hA, hB);
                u64 hpA = pk(hA, hA), hpB = pk(hB, hB);
                ulonglong2 q0 = *(const ulonglong2*)&WQ[u][wid][0];
                ulonglong2 q1 = *(const ulonglong2*)&WQ[u][wid][2];
                aA[0] = fma2(q0.x, hpA, aA[0]);  aB[0] = fma2(q0.x, hpB, aB[0]);
                aA[1] = fma2(q0.y, hpA, aA[1]);  aB[1] = fma2(q0.y, hpB, aB[1]);
                aA[2] = fma2(q1.x, hpA, aA[2]);  aB[2] = fma2(q1.x, hpB, aB[2]);
                aA[3] = fma2(q1.y, hpA, aA[3]);  aB[3] = fma2(q1.y, hpB, aB[3]);
            }
            // cells: slot s holds gate s of (unit ub -> lo, unit ub+1 -> hi)
            float iA0,iA1,fA0,fA1,gA0,gA1,oA0,oA1;
            float iB0,iB1,fB0,fB1,gB0,gB1,oB0,oB1;
            upk(aA[0],iA0,iA1); upk(aA[1],fA0,fA1);
            upk(aA[2],gA0,gA1); upk(aA[3],oA0,oA1);
            upk(aB[0],iB0,iB1); upk(aB[1],fB0,fB1);
            upk(aB[2],gB0,gB1); upk(aB[3],oB0,oB1);

            float cA, cB, hA, hB;
            upk(c2[0], cA, cB);
            cell(iA0, fA0, gA0, oA0, cA, hA);
            cell(iB0, fB0, gB0, oB0, cB, hB);
            c2[0] = pk(cA, cB);
            *(u64*)&h_s[nxt][ub][rA] = pk(hA, hB);

            upk(c2[1], cA, cB);
            cell(iA1, fA1, gA1, oA1, cA, hA);
            cell(iB1, fB1, gB1, oB1, cB, hB);
            c2[1] = pk(cA, cB);
            *(u64*)&h_s[nxt][ub + 1][rA] = pk(hA, hB);
        } else {
#pragma unroll
            for (int u = PSRC; u < H; ++u) {
                float hA, hB; upk(h2[u], hA, hB);
                u64 hpA = pk(hA, hA), hpB = pk(hB, hB);
                ulonglong2 q0 = *(const ulonglong2*)&WQ[u][wid][0];
                aA[0] = fma2(q0.x, hpA, aA[0]);  aB[0] = fma2(q0.x, hpB, aB[0]);
                aA[1] = fma2(q0.y, hpA, aA[1]);  aB[1] = fma2(q0.y, hpB, aB[1]);
            }
            // slot 0 = (i,f); slot 1 = (g,o), single unit ub
            float ifA0, ifA1, goA0, goA1, ifB0, ifB1, goB0, goB1;
            upk(aA[0], ifA0, ifA1); upk(aA[1], goA0, goA1);
            upk(aB[0], ifB0, ifB1); upk(aB[1], goB0, goB1);

            float cA, cB, hA, hB;
            upk(c2[0], cA, cB);
            cell(ifA0, ifA1, goA0, goA1, cA, hA);
            cell(ifB0, ifB1, goB0, goB1, cB, hB);
            c2[0] = pk(cA, cB);
            *(u64*)&h_s[nxt][ub][rA] = pk(hA, hB);
        }

        // single barrier per step: publish h(t+1), protect buffer swap
        __syncthreads();

        xv = xnext;
    }

    // final out[T-1] from buffer (T_DIM & 1)
    if (wid == 8) {
        const int cur = T_DIM & 1;
        u64 oacc = pk(b2_s, b2_s);
#pragma unroll
        for (int u = 0; u < H; ++u)
            oacc = fma2(w2p[u], *(const u64*)&h_s[cur][u][rA], oacc);
        float o0, o1; upk(oacc, o0, o1);
        *(float2*)(g_outT + (size_t)(T_DIM - 1) * B_DIM + rowbase + rA) =
            make_float2(o0, o1);
    }
}

// ---------------- launcher ----------------
extern "C" void kernel_launch(void* const* d_in, const int* in_sizes, int n_in,
                              void* d_out, int out_size)
{
    const float* x    = (const float*)d_in[0];
    const float* W1   = (const float*)d_in[1];
    const float* b1   = (const float*)d_in[2];
    const float* W_ih = (const float*)d_in[3];
    const float* W_hh = (const float*)d_in[4];
    const float* b_ih = (const float*)d_in[5];
    const float* b_hh = (const float*)d_in[6];
    const float* W2   = (const float*)d_in[7];
    const float* b2   = (const float*)d_in[8];
    float* out = (float*)d_out;

    (void)in_sizes; (void)n_in; (void)out_size;

    // x[B][T] -> g_xT[T][B]
    transpose_in<<<dim3(T_DIM / 32, B_DIM / 32), dim3(32, 8)>>>(x);

    // recurrent scan: 128 CTAs x 384 threads, 3 warps/SMSP, units covered once
    lstm_kernel<<<B_DIM / CTA_ROWS, NTHR>>>(W1, b1, W_ih, W_hh, b_ih, b_hh, W2, b2);

    // g_outT[T][B] -> out[B][T]
    transpose_out<<<dim3(B_DIM / 32, T_DIM / 32), dim3(32, 8)>>>(out);
}

// round 15
// speedup vs baseline: 1.4197x; 1.0556x over previous
#include <cuda_runtime.h>

// Problem dims (fixed by reference setup_inputs)
#define B_DIM 8192
#define T_DIM 2048
#define H     20
#define CTA_ROWS 64       // batch rows per CTA
#define NTHR  256         // 8 warps; warps 0-3 own 3 units, warps 4-7 own 2
#define PSRC  8           // source units pinned in registers

typedef unsigned long long u64;

// Scratch (allocation-free rule: __device__ globals)
__device__ float g_xT[(size_t)T_DIM * B_DIM];   // x transposed: [t][b]
__device__ float g_outT[(size_t)T_DIM * B_DIM]; // out transposed: [t][b]

// ---------------- f32x2 helpers ----------------
__device__ __forceinline__ u64 pk(float lo, float hi) {
    u64 r; asm("mov.b64 %0,{%1,%2};" : "=l"(r) : "f"(lo), "f"(hi)); return r;
}
__device__ __forceinline__ void upk(u64 v, float& lo, float& hi) {
    asm("mov.b64 {%0,%1},%2;" : "=f"(lo), "=f"(hi) : "l"(v));
}
__device__ __forceinline__ u64 fma2(u64 a, u64 b, u64 c) {
    u64 d; asm("fma.rn.f32x2 %0,%1,%2,%3;" : "=l"(d) : "l"(a), "l"(b), "l"(c)); return d;
}
__device__ __forceinline__ float tanh_a(float x) {
    float r; asm("tanh.approx.f32 %0,%1;" : "=f"(r) : "f"(x)); return r;
}

// LSTM cell via MUFU.TANH: 5 MUFU + ~9 FMA-pipe ops.
__device__ __forceinline__ void cell(float ig, float fg, float gg, float og,
                                     float& c, float& h) {
    float si = fmaf(0.5f, tanh_a(0.5f * ig), 0.5f);
    float sf = fmaf(0.5f, tanh_a(0.5f * fg), 0.5f);
    float so = fmaf(0.5f, tanh_a(0.5f * og), 0.5f);
    float tg = tanh_a(gg);
    float cn = sf * c + si * tg;
    float tc = tanh_a(cn);
    c = cn;
    h = so * tc;
}

// ---------------- transposes ----------------
__global__ void transpose_in(const float* __restrict__ in) {
    __shared__ float tile[32][33];
    int c0 = blockIdx.x * 32, r0 = blockIdx.y * 32;
    int tx = threadIdx.x, ty = threadIdx.y;
#pragma unroll
    for (int i = 0; i < 32; i += 8)
        tile[ty + i][tx] = in[(size_t)(r0 + ty + i) * T_DIM + c0 + tx];
    __syncthreads();
#pragma unroll
    for (int i = 0; i < 32; i += 8)
        g_xT[(size_t)(c0 + ty + i) * B_DIM + r0 + tx] = tile[tx][ty + i];
}

__global__ void transpose_out(float* __restrict__ out) {
    __shared__ float tile[32][33];
    int c0 = blockIdx.x * 32, r0 = blockIdx.y * 32;
    int tx = threadIdx.x, ty = threadIdx.y;
#pragma unroll
    for (int i = 0; i < 32; i += 8)
        tile[ty + i][tx] = g_outT[(size_t)(r0 + ty + i) * B_DIM + c0 + tx];
    __syncthreads();
#pragma unroll
    for (int i = 0; i < 32; i += 8)
        out[(size_t)(c0 + ty + i) * T_DIM + r0 + tx] = tile[tx][ty + i];
}

// Slot -> (gate-row ka, gate-row kb) mapping.
// Warps 0-3: units ub=3w,3w+1,3w+2. Slots 0-3: gate s of pair (ub,ub+1).
//            Slot 4: (i,f) of ub+2. Slot 5: (g,o) of ub+2.
// Warps 4-7: units ub=12+2(w-4). Slots 0-3 only.
__device__ __forceinline__ bool slot_rows(int w, int s, int& ka, int& kb) {
    if (w < 4) {
        int ub = 3 * w;
        if (s < 4)      { ka = s * H + ub;     kb = ka + 1; }
        else if (s == 4){ ka = 0 * H + ub + 2; kb = 1 * H + ub + 2; }
        else            { ka = 2 * H + ub + 2; kb = 3 * H + ub + 2; }
        return true;
    } else {
        int ub = 12 + 2 * (w - 4);
        if (s < 4) { ka = s * H + ub; kb = ka + 1; return true; }
        return false;
    }
}

// ---------------- main persistent LSTM kernel ----------------
// 128 CTAs x 256 threads (8 warps) — round-11 structure (best: 1879 us).
// Lane owns rows (2l, 2l+1); SMSP k runs heavy warp k (3 units) + light warp
// k+4 (2 units) = 5 units -> FMA balanced ~840 cyc/SMSP. One barrier/step.
// ROUND-15 CHANGES vs round 11 (structure otherwise identical):
//  (a) out-projection rotates across LIGHT warps 4-7 (t&3) — round 11 pinned
//      it to wid 4, overloading SMSP 0 every step.
//  (b) heavy path interleaves FMA and MUFU: pair-slot accumulation (0-3) ->
//      pair cells (MUFU) -> solo-slot accumulation (4-5, 80 independent
//      FFMA2 that the scheduler issues under the tanh chains) -> solo cell.
//      Per-accumulator summation order unchanged -> bitwise-identical output.
__global__ __launch_bounds__(NTHR, 1) void lstm_kernel(
    const float* __restrict__ W1, const float* __restrict__ b1,
    const float* __restrict__ W_ih, const float* __restrict__ W_hh,
    const float* __restrict__ b_ih, const float* __restrict__ b_hh,
    const float* __restrict__ W2, const float* __restrict__ b2)
{
    __shared__ __align__(16) u64 WQ[H][8][6];     // [src][warp][slot]  7.7 KB
    __shared__ __align__(16) u64 uvu[8][6], uvv[8][6];
    __shared__ u64 w2p[H];                        // (W2[u], W2[u]) duplicated
    __shared__ float b2_s;
    __shared__ __align__(8) float h_s[2][H][CTA_ROWS];  // 10.2 KB

    const int tid  = threadIdx.x;
    const int lane = tid & 31;
    const int wid  = tid >> 5;
    const int rowbase = blockIdx.x * CTA_ROWS;
    const int rA = 2 * lane;

    // --- one-time setup ---
    for (int i = tid; i < H * 48; i += NTHR) {
        int src = i / 48, r = i % 48, w = r / 6, s = r % 6;
        int ka, kb;
        WQ[src][w][s] = slot_rows(w, s, ka, kb)
            ? pk(W_hh[ka * H + src], W_hh[kb * H + src]) : 0ULL;
    }
    if (tid < 48) {
        int w = tid / 6, s = tid % 6, ka, kb;
        if (slot_rows(w, s, ka, kb)) {
            float sua = 0.f, sva = 0.f, sub = 0.f, svb = 0.f;
            for (int u = 0; u < H; ++u) {
                sua += W_ih[ka * H + u] * W1[u];
                sva += W_ih[ka * H + u] * b1[u];
                sub += W_ih[kb * H + u] * W1[u];
                svb += W_ih[kb * H + u] * b1[u];
            }
            uvu[w][s] = pk(sua, sub);
            uvv[w][s] = pk(sva + b_ih[ka] + b_hh[ka], svb + b_ih[kb] + b_hh[kb]);
        } else { uvu[w][s] = 0ULL; uvv[w][s] = 0ULL; }
    }
    if (tid < H) { float wv = W2[tid]; w2p[tid] = pk(wv, wv); }
    if (tid == 0) b2_s = b2[0];
    for (int i = tid; i < 2 * H * CTA_ROWS; i += NTHR) h_s[0][0][i] = 0.f;
    __syncthreads();

    const int ub = (wid < 4) ? 3 * wid : 12 + 2 * (wid - 4);

    // per-warp register tables (6 slots, light warps just ignore 4/5)
    u64 uu[6], vv[6];
#pragma unroll
    for (int s = 0; s < 6; ++s) { uu[s] = uvu[wid][s]; vv[s] = uvv[wid][s]; }

    // pinned weights for sources [0, PSRC): 48 u64 = 96 regs (heavy path)
    u64 wp[PSRC][6];
#pragma unroll
    for (int u = 0; u < PSRC; ++u)
#pragma unroll
        for (int s = 0; s < 6; ++s) wp[u][s] = WQ[u][wid][s];

    u64 c2[3] = {0ULL, 0ULL, 0ULL};   // cell state per owned unit: (rowA, rowB)

    float2 xv = *(const float2*)(g_xT + rowbase + rA);

    for (int t = 0; t < T_DIM; ++t) {
        const int cur = t & 1, nxt = cur ^ 1;

        float2 xnext = xv;
        if (t + 1 < T_DIM)
            xnext = *(const float2*)(g_xT + (size_t)(t + 1) * B_DIM + rowbase + rA);

        // ---- preload full h vector (u64 = (h[rowA], h[rowB])) ----
        u64 h2[H];
#pragma unroll
        for (int u = 0; u < H; ++u)
            h2[u] = *(const u64*)&h_s[cur][u][rA];

        // ---- out[t-1]: ROTATES across light warps 4-7 (deload SMSP 0) ----
        if (t > 0 && wid == 4 + (t & 3)) {
            u64 oacc = pk(b2_s, b2_s);
#pragma unroll
            for (int u = 0; u < H; ++u)
                oacc = fma2(w2p[u], h2[u], oacc);    // (outA, outB)
            float o0, o1; upk(oacc, o0, o1);
            *(float2*)(g_outT + (size_t)(t - 1) * B_DIM + rowbase + rA) =
                make_float2(o0, o1);
        }

        u64 xA2 = pk(xv.x, xv.x), xB2 = pk(xv.y, xv.y);

        if (wid < 4) {
            // ===== heavy path, interleaved =====
            // Stage 1: pair slots 0-3 (units ub, ub+1) over all sources.
            u64 aA[4], aB[4];
#pragma unroll
            for (int s = 0; s < 4; ++s) {
                aA[s] = fma2(xA2, uu[s], vv[s]);
                aB[s] = fma2(xB2, uu[s], vv[s]);
            }
#pragma unroll
            for (int u = 0; u < PSRC; ++u) {
                float hA, hB; upk(h2[u], hA, hB);
                u64 hpA = pk(hA, hA), hpB = pk(hB, hB);
#pragma unroll
                for (int s = 0; s < 4; ++s) {
                    aA[s] = fma2(wp[u][s], hpA, aA[s]);
                    aB[s] = fma2(wp[u][s], hpB, aB[s]);
                }
            }
#pragma unroll
            for (int u = PSRC; u < H; ++u) {
                float hA, hB; upk(h2[u], hA, hB);
                u64 hpA = pk(hA, hA), hpB = pk(hB, hB);
                ulonglong2 q0 = *(const ulonglong2*)&WQ[u][wid][0];
                ulonglong2 q1 = *(const ulonglong2*)&WQ[u][wid][2];
                aA[0] = fma2(q0.x, hpA, aA[0]);  aB[0] = fma2(q0.x, hpB, aB[0]);
                aA[1] = fma2(q0.y, hpA, aA[1]);  aB[1] = fma2(q0.y, hpB, aB[1]);
                aA[2] = fma2(q1.x, hpA, aA[2]);  aB[2] = fma2(q1.x, hpB, aB[2]);
                aA[3] = fma2(q1.y, hpA, aA[3]);  aB[3] = fma2(q1.y, hpB, aB[3]);
            }

            // Stage 2: pair cells (MUFU chains) — independent of stage 3.
            float iA0,iA1,fA0,fA1,gA0,gA1,oA0,oA1;
            float iB0,iB1,fB0,fB1,gB0,gB1,oB0,oB1;
            upk(aA[0],iA0,iA1); upk(aA[1],fA0,fA1);
            upk(aA[2],gA0,gA1); upk(aA[3],oA0,oA1);
            upk(aB[0],iB0,iB1); upk(aB[1],fB0,fB1);
            upk(aB[2],gB0,gB1); upk(aB[3],oB0,oB1);

            float cA, cB, hA, hB;
            upk(c2[0], cA, cB);
            cell(iA0, fA0, gA0, oA0, cA, hA);
            cell(iB0, fB0, gB0, oB0, cB, hB);
            c2[0] = pk(cA, cB);
            *(u64*)&h_s[nxt][ub][rA] = pk(hA, hB);

            upk(c2[1], cA, cB);
            cell(iA1, fA1, gA1, oA1, cA, hA);
            cell(iB1, fB1, gB1, oB1, cB, hB);
            c2[1] = pk(cA, cB);
            *(u64*)&h_s[nxt][ub + 1][rA] = pk(hA, hB);

            // Stage 3: solo slots 4-5 (unit ub+2) — 80 independent FFMA2 the
            // scheduler issues under stage 2's tanh chains.
            u64 sA0 = fma2(xA2, uu[4], vv[4]), sB0 = fma2(xB2, uu[4], vv[4]);
            u64 sA1 = fma2(xA2, uu[5], vv[5]), sB1 = fma2(xB2, uu[5], vv[5]);
#pragma unroll
            for (int u = 0; u < PSRC; ++u) {
                float h0, h1; upk(h2[u], h0, h1);
                u64 hpA = pk(h0, h0), hpB = pk(h1, h1);
                sA0 = fma2(wp[u][4], hpA, sA0);  sB0 = fma2(wp[u][4], hpB, sB0);
                sA1 = fma2(wp[u][5], hpA, sA1);  sB1 = fma2(wp[u][5], hpB, sB1);
            }
#pragma unroll
            for (int u = PSRC; u < H; ++u) {
                float h0, h1; upk(h2[u], h0, h1);
                u64 hpA = pk(h0, h0), hpB = pk(h1, h1);
                ulonglong2 q2 = *(const ulonglong2*)&WQ[u][wid][4];
                sA0 = fma2(q2.x, hpA, sA0);  sB0 = fma2(q2.x, hpB, sB0);
                sA1 = fma2(q2.y, hpA, sA1);  sB1 = fma2(q2.y, hpB, sB1);
            }
            // Stage 4: solo cell (unit ub+2): slot4=(i,f), slot5=(g,o)
            float ifA0, ifA1, goA0, goA1, ifB0, ifB1, goB0, goB1;
            upk(sA0, ifA0, ifA1); upk(sA1, goA0, goA1);
            upk(sB0, ifB0, ifB1); upk(sB1, goB0, goB1);

            upk(c2[2], cA, cB);
            cell(ifA0, ifA1, goA0, goA1, cA, hA);
            cell(ifB0, ifB1, goB0, goB1, cB, hB);
            c2[2] = pk(cA, cB);
            *(u64*)&h_s[nxt][ub + 2][rA] = pk(hA, hB);
        } else {
            // ===== light path: 2 units, 4 slots (unchanged from round 11) =====
            u64 aA[4], aB[4];
#pragma unroll
            for (int s = 0; s < 4; ++s) {
                aA[s] = fma2(xA2, uu[s], vv[s]);
                aB[s] = fma2(xB2, uu[s], vv[s]);
            }
#pragma unroll
            for (int u = 0; u < PSRC; ++u) {
                float hA, hB; upk(h2[u], hA, hB);
                u64 hpA = pk(hA, hA), hpB = pk(hB, hB);
#pragma unroll
                for (int s = 0; s < 4; ++s) {
                    aA[s] = fma2(wp[u][s], hpA, aA[s]);
                    aB[s] = fma2(wp[u][s], hpB, aB[s]);
                }
            }
#pragma unroll
            for (int u = PSRC; u < H; ++u) {
                float hA, hB; upk(h2[u], hA, hB);
                u64 hpA = pk(hA, hA), hpB = pk(hB, hB);
                ulonglong2 q0 = *(const ulonglong2*)&WQ[u][wid][0];
                ulonglong2 q1 = *(const ulonglong2*)&WQ[u][wid][2];
                aA[0] = fma2(q0.x, hpA, aA[0]);  aB[0] = fma2(q0.x, hpB, aB[0]);
                aA[1] = fma2(q0.y, hpA, aA[1]);  aB[1] = fma2(q0.y, hpB, aB[1]);
                aA[2] = fma2(q1.x, hpA, aA[2]);  aB[2] = fma2(q1.x, hpB, aB[2]);
                aA[3] = fma2(q1.y, hpA, aA[3]);  aB[3] = fma2(q1.y, hpB, aB[3]);
            }
            float iA0,iA1,fA0,fA1,gA0,gA1,oA0,oA1;
            float iB0,iB1,fB0,fB1,gB0,gB1,oB0,oB1;
            upk(aA[0],iA0,iA1); upk(aA[1],fA0,fA1);
            upk(aA[2],gA0,gA1); upk(aA[3],oA0,oA1);
            upk(aB[0],iB0,iB1); upk(aB[1],fB0,fB1);
            upk(aB[2],gB0,gB1); upk(aB[3],oB0,oB1);

            float cA, cB, hA, hB;
            upk(c2[0], cA, cB);
            cell(iA0, fA0, gA0, oA0, cA, hA);
            cell(iB0, fB0, gB0, oB0, cB, hB);
            c2[0] = pk(cA, cB);
            *(u64*)&h_s[nxt][ub][rA] = pk(hA, hB);

            upk(c2[1], cA, cB);
            cell(iA1, fA1, gA1, oA1, cA, hA);
            cell(iB1, fB1, gB1, oB1, cB, hB);
            c2[1] = pk(cA, cB);
            *(u64*)&h_s[nxt][ub + 1][rA] = pk(hA, hB);
        }

        // single barrier per step (top-level: all 256 threads arrive)
        __syncthreads();

        xv = xnext;
    }

    // final out[T-1] from buffer (T_DIM & 1)
    if (wid == 4) {
        const int cur = T_DIM & 1;
        u64 oacc = pk(b2_s, b2_s);
#pragma unroll
        for (int u = 0; u < H; ++u)
            oacc = fma2(w2p[u], *(const u64*)&h_s[cur][u][rA], oacc);
        float o0, o1; upk(oacc, o0, o1);
        *(float2*)(g_outT + (size_t)(T_DIM - 1) * B_DIM + rowbase + rA) =
            make_float2(o0, o1);
    }
}

// ---------------- launcher ----------------
extern "C" void kernel_launch(void* const* d_in, const int* in_sizes, int n_in,
                              void* d_out, int out_size)
{
    const float* x    = (const float*)d_in[0];
    const float* W1   = (const float*)d_in[1];
    const float* b1   = (const float*)d_in[2];
    const float* W_ih = (const float*)d_in[3];
    const float* W_hh = (const float*)d_in[4];
    const float* b_ih = (const float*)d_in[5];
    const float* b_hh = (const float*)d_in[6];
    const float* W2   = (const float*)d_in[7];
    const float* b2   = (const float*)d_in[8];
    float* out = (float*)d_out;

    (void)in_sizes; (void)n_in; (void)out_size;

    // x[B][T] -> g_xT[T][B]
    transpose_in<<<dim3(T_DIM / 32, B_DIM / 32), dim3(32, 8)>>>(x);

    // recurrent scan: 128 CTAs x 256 threads, SMSP-balanced, FMA/MUFU interleave
    lstm_kernel<<<B_DIM / CTA_ROWS, NTHR>>>(W1, b1, W_ih, W_hh, b_ih, b_hh, W2, b2);

    // g_outT[T][B] -> out[B][T]
    transpose_out<<<dim3(B_DIM / 32, T_DIM / 32), dim3(32, 8)>>>(out);
}